// round 3
// baseline (speedup 1.0000x reference)
#include <cuda_runtime.h>
#include <cuda_bf16.h>

// Problem constants
#define V_  20000
#define M_  32
#define E_  128
#define H_  4
#define N_  8192
#define L_  64
#define C_  128

// ---------------- device scratch (no allocations allowed) ----------------
__device__ float g_word_embeds[V_ * E_];          // [V,E]
__device__ float g_wt3[E_ * 3 * C_];              // [(e*3+j)*128 + c]
__device__ float g_wt4[E_ * 4 * C_];
__device__ float g_wt5[E_ * 5 * C_];

// ---------------- f32x2 helpers ----------------
__device__ __forceinline__ unsigned long long pk2(float x, float y) {
    unsigned long long r;
    asm("mov.b64 %0, {%1,%2};" : "=l"(r) : "f"(x), "f"(y));
    return r;
}
__device__ __forceinline__ void unpk(unsigned long long v, float& x, float& y) {
    asm("mov.b64 {%0,%1}, %2;" : "=f"(x), "=f"(y) : "l"(v));
}
__device__ __forceinline__ unsigned long long ffma2(unsigned long long a,
                                                    unsigned long long b,
                                                    unsigned long long c) {
    unsigned long long d;
    asm("fma.rn.f32x2 %0, %1, %2, %3;" : "=l"(d) : "l"(a), "l"(b), "l"(c));
    return d;
}

// ---------------- weight transpose kernels: [C][E][K] -> [(e*K+j)*128 + c] ----
template <int K>
__global__ void transpose_w_kernel(const float* __restrict__ w, float* __restrict__ wt) {
    int i = blockIdx.x * blockDim.x + threadIdx.x;
    const int total = C_ * E_ * K;
    if (i < total) {
        int c = i / (E_ * K);
        int r = i - c * (E_ * K);   // e*K + j
        wt[r * C_ + c] = w[i];
    }
}

// ---------------- word embedding kernel: one block per word ----------------
// Key algebra (single query):
//   scores[h,m] = (ctx[m] . g_h + qh_h.bk_h) / sqrt(Dh),  g_h[e] = sum_d qh[h*32+d]*Wk[h*32+d][e]
//   o[i] = ch_{h(i)} . Wv[i] + bv[i],                      ch_h[e] = sum_m attn[h,m]*ctx[m][e]
__global__ __launch_bounds__(128) void word_embed_kernel(
    const int* __restrict__ word2news, const int* __restrict__ word2news_len,
    const float* __restrict__ table,
    const float* __restrict__ in_w, const float* __restrict__ in_b,
    const float* __restrict__ out_w, const float* __restrict__ out_b)
{
    __shared__ float ctx[M_][E_ + 1];   // padded to kill bank conflicts
    __shared__ float q_s[E_], qh_s[E_], o_s[E_];
    __shared__ float g_s[H_][E_], ch_s[H_][E_];
    __shared__ float attn_s[H_][M_];
    __shared__ float cb_s[H_];
    __shared__ int idx_s[M_];

    const int v = blockIdx.x;
    const int tid = threadIdx.x;
    const int len = word2news_len[v];

    if (tid < M_) idx_s[tid] = word2news[v * M_ + tid];
    __syncthreads();

    #pragma unroll 4
    for (int m = 0; m < M_; ++m)
        ctx[m][tid] = table[idx_s[m] * E_ + tid];
    __syncthreads();

    // masked mean query
    {
        float inv_cnt = 1.0f / (float)(len > 0 ? len : 1);
        float s = 0.0f;
        for (int m = 0; m < len; ++m) s += ctx[m][tid];
        q_s[tid] = s * inv_cnt;
    }
    __syncthreads();

    // qh = q @ Wq^T + bq
    {
        float a = in_b[tid];
        const float* wq = in_w + tid * E_;
        #pragma unroll 8
        for (int e = 0; e < E_; ++e) a += q_s[e] * wq[e];
        qh_s[tid] = a;
    }
    __syncthreads();

    // g_h[e] = sum_d qh[h*32+d] * Wk[h*32+d][e];  cb_h = qh_h . bk_h
    #pragma unroll
    for (int h = 0; h < H_; ++h) {
        float gg = 0.0f;
        #pragma unroll 8
        for (int d = 0; d < 32; ++d)
            gg += qh_s[h * 32 + d] * in_w[(E_ + h * 32 + d) * E_ + tid];
        g_s[h][tid] = gg;
    }
    if (tid < H_) {
        float c = 0.0f;
        for (int d = 0; d < 32; ++d) c += qh_s[tid * 32 + d] * in_b[E_ + tid * 32 + d];
        cb_s[tid] = c;
    }
    __syncthreads();

    // scores + per-head warp softmax: thread = (h = tid>>5, m = lane)
    {
        const int h = tid >> 5, m = tid & 31;
        float sc = cb_s[h];
        #pragma unroll 8
        for (int e = 0; e < E_; ++e) sc += ctx[m][e] * g_s[h][e];
        sc *= 0.17677669529663688f;               // 1/sqrt(32)
        if (m >= len) sc = -1e30f;
        float wm = sc;
        #pragma unroll
        for (int o = 16; o; o >>= 1) wm = fmaxf(wm, __shfl_xor_sync(0xFFFFFFFFu, wm, o));
        float p = __expf(sc - wm);
        float ps = p;
        #pragma unroll
        for (int o = 16; o; o >>= 1) ps += __shfl_xor_sync(0xFFFFFFFFu, ps, o);
        attn_s[h][m] = p / ps;
    }
    __syncthreads();

    // ch_h[e] = sum_m attn[h,m]*ctx[m][e]
    #pragma unroll
    for (int h = 0; h < H_; ++h) {
        float c = 0.0f;
        #pragma unroll 8
        for (int m = 0; m < M_; ++m) c += attn_s[h][m] * ctx[m][tid];
        ch_s[h][tid] = c;
    }
    __syncthreads();

    // o[i] = ch_{h} . Wv[i] + bv[i]
    {
        const int h = tid >> 5;
        float oo = in_b[2 * E_ + tid];
        const float* wv = in_w + (2 * E_ + tid) * E_;
        #pragma unroll 8
        for (int e = 0; e < E_; ++e) oo += ch_s[h][e] * wv[e];
        o_s[tid] = oo;
    }
    __syncthreads();

    // out proj
    {
        float r = out_b[tid];
        const float* wo = out_w + tid * E_;
        #pragma unroll 8
        for (int e = 0; e < E_; ++e) r += o_s[e] * wo[e];
        g_word_embeds[v * E_ + tid] = (len > 0) ? r : 0.0f;
    }
}

// ---------------- conv + maxpool + FC kernel: one block per news item -----
// Thread layout: 128 threads = {half = tid>>6} x {pair = tid&63 -> channels 2p,2p+1}
// Each thread computes 31 t-positions for its channel pair via packed f32x2 FMA.
template <int K>
__device__ __forceinline__ void conv_phase(
    const unsigned long long* __restrict__ wt,  // float2 rows: [(e*K+j)*64 + pair]
    const float* __restrict__ bias,
    const float (*doc_s)[E_],
    int half, int pair, int c0,
    float* ph, float* feats_s, int kidx)
{
    constexpr int T = L_ - K + 1;          // 62 / 61 / 60
    const int tlo = half ? (T - 31) : 0;   // halves overlap slightly; max is idempotent

    unsigned long long acc[31];
    #pragma unroll
    for (int t = 0; t < 31; ++t) acc[t] = 0ULL;

    for (int e = 0; e < E_; ++e) {
        unsigned long long w2[K];
        #pragma unroll
        for (int j = 0; j < K; ++j) w2[j] = wt[(e * K + j) * 64 + pair];

        #pragma unroll
        for (int t0 = 0; t0 < 31; t0 += 8) {
            const int CN = (31 - t0 < 8) ? (31 - t0) : 8;
            unsigned long long dpk[8 + K - 1];
            #pragma unroll
            for (int x = 0; x < CN + K - 1; ++x) {
                float d = doc_s[tlo + t0 + x][e];   // warp-uniform -> smem broadcast
                dpk[x] = pk2(d, d);
            }
            #pragma unroll
            for (int tt = 0; tt < CN; ++tt) {
                #pragma unroll
                for (int j = 0; j < K; ++j)
                    acc[t0 + tt] = ffma2(dpk[tt + j], w2[j], acc[t0 + tt]);
            }
        }
    }

    float mx = -1e30f, my = -1e30f;
    #pragma unroll
    for (int t = 0; t < 31; ++t) {
        float x, y;
        unpk(acc[t], x, y);
        mx = fmaxf(mx, x);
        my = fmaxf(my, y);
    }
    ph[half * 128 + 2 * pair]     = mx;
    ph[half * 128 + 2 * pair + 1] = my;
    __syncthreads();
    if (half == 0) {
        float a = fmaxf(ph[2 * pair],     ph[128 + 2 * pair]);
        float b = fmaxf(ph[2 * pair + 1], ph[128 + 2 * pair + 1]);
        // max_t relu(y+b) == relu(b + max_t y)
        a = fmaxf(a + bias[c0], 0.0f);
        b = fmaxf(b + bias[c0 + 1], 0.0f);
        feats_s[kidx * C_ + c0]     = a;
        feats_s[kidx * C_ + c0 + 1] = b;
    }
    __syncthreads();
}

__global__ __launch_bounds__(128) void conv_fc_kernel(
    const int* __restrict__ news_words,
    const float* __restrict__ b3, const float* __restrict__ b4, const float* __restrict__ b5,
    const float* __restrict__ fc_w, const float* __restrict__ fc_b,
    float* __restrict__ out)
{
    __shared__ float doc_s[L_][E_];
    __shared__ float ph[256];
    __shared__ float feats_s[3 * C_];
    __shared__ int idx_s[L_];

    const int n = blockIdx.x;
    const int tid = threadIdx.x;

    if (tid < L_) idx_s[tid] = news_words[n * L_ + tid];
    __syncthreads();

    #pragma unroll 4
    for (int l = 0; l < L_; ++l)
        doc_s[l][tid] = g_word_embeds[idx_s[l] * E_ + tid];
    __syncthreads();

    const int half = tid >> 6;
    const int pair = tid & 63;
    const int c0 = 2 * pair;

    conv_phase<3>((const unsigned long long*)g_wt3, b3, doc_s, half, pair, c0, ph, feats_s, 0);
    conv_phase<4>((const unsigned long long*)g_wt4, b4, doc_s, half, pair, c0, ph, feats_s, 1);
    conv_phase<5>((const unsigned long long*)g_wt5, b5, doc_s, half, pair, c0, ph, feats_s, 2);

    // FC epilogue: out[n, tid] = fc_b[tid] + feats . fc_w[tid, :]
    float acc = fc_b[tid];
    const float* wrow = fc_w + tid * (3 * C_);
    #pragma unroll 8
    for (int i = 0; i < 3 * C_; ++i) acc += feats_s[i] * wrow[i];
    out[n * E_ + tid] = acc;
}

// ---------------- launch ----------------
extern "C" void kernel_launch(void* const* d_in, const int* in_sizes, int n_in,
                              void* d_out, int out_size) {
    const int*   word2news     = (const int*)d_in[0];
    const int*   word2news_len = (const int*)d_in[1];
    const int*   news_words    = (const int*)d_in[2];
    const float* table         = (const float*)d_in[3];
    const float* in_w          = (const float*)d_in[4];
    const float* in_b          = (const float*)d_in[5];
    const float* out_w         = (const float*)d_in[6];
    const float* out_b         = (const float*)d_in[7];
    const float* w3            = (const float*)d_in[8];
    const float* b3            = (const float*)d_in[9];
    const float* w4            = (const float*)d_in[10];
    const float* b4            = (const float*)d_in[11];
    const float* w5            = (const float*)d_in[12];
    const float* b5            = (const float*)d_in[13];
    const float* fc_w          = (const float*)d_in[14];
    const float* fc_b          = (const float*)d_in[15];
    float* out = (float*)d_out;

    // weight transposes (tiny)
    {
        float* wt3; cudaGetSymbolAddress((void**)&wt3, g_wt3);
        float* wt4; cudaGetSymbolAddress((void**)&wt4, g_wt4);
        float* wt5; cudaGetSymbolAddress((void**)&wt5, g_wt5);
        transpose_w_kernel<3><<<(C_*E_*3 + 255) / 256, 256>>>(w3, wt3);
        transpose_w_kernel<4><<<(C_*E_*4 + 255) / 256, 256>>>(w4, wt4);
        transpose_w_kernel<5><<<(C_*E_*5 + 255) / 256, 256>>>(w5, wt5);
    }

    word_embed_kernel<<<V_, 128>>>(word2news, word2news_len, table,
                                   in_w, in_b, out_w, out_b);

    conv_fc_kernel<<<N_, 128>>>(news_words, b3, b4, b5, fc_w, fc_b, out);
}